// round 13
// baseline (speedup 1.0000x reference)
#include <cuda_runtime.h>

#define NBINS  10
#define NSLOTS 11          // 10 real bins + 1 dead slot (g >= 1)
#define NT     256
#define GRID   1216        // 8 CTAs * 152 SMs (GB300), single resident wave
#define TSTRIDE (GRID * NT)

// Per-block partials: every block overwrites its own slot -> no zeroing pass.
__device__ float2   g_part[GRID][NBINS];
__device__ unsigned g_ticket;   // zero-init at load; last block resets each call

// ln(1+x) on x in (0,1] via degree-6 Taylor at x0=0.5 (|u|<=0.5, term ratio
// 1/3 -> abs err ~5e-5; fma-pipe work replaces the MUFU.LG2 + FMUL + FADD).
__device__ __forceinline__ float log1p_poly(float x) {
    float u = x - 0.5f;
    float r = -0.014631916f;
    r = fmaf(r, u,  0.026337449f);
    r = fmaf(r, u, -0.049382716f);
    r = fmaf(r, u,  0.098765432f);
    r = fmaf(r, u, -0.222222222f);
    r = fmaf(r, u,  0.666666667f);
    r = fmaf(r, u,  0.405465108f);   // ln(1.5)
    return r;
}

__device__ __forceinline__ void ghmc_acc(float p, float t, float2* __restrict__ h) {
    // slot = min(floor(10*|p-t|), 10); slot 10 is dead (discarded later).
    float g10 = fabsf(p - t) * 10.0f;
    int  slot = min((int)g10, NSLOTS - 1);

    // bce = t*p - softplus(p);  softplus(p) = max(p,0) + ln(1+exp(-|p|))
    float e   = __expf(-fabsf(p));
    float l   = log1p_poly(e);               // was: __logf(1.0f + e)
    float bce = t * p - fmaxf(p, 0.0f) - l;

    float2 a = h[slot * NT];   // stride NT*8B: conflict-free across lanes
    a.x += bce;
    a.y += 1.0f;
    h[slot * NT] = a;
}

__device__ __forceinline__ void ghmc_acc4(float4 p, float4 t,
                                          float2* __restrict__ h) {
    ghmc_acc(p.x, t.x, h);
    ghmc_acc(p.y, t.y, h);
    ghmc_acc(p.z, t.z, h);
    ghmc_acc(p.w, t.w, h);
}

__global__ __launch_bounds__(NT) void ghmc_kernel(
    const float4* __restrict__ pred,
    const float4* __restrict__ targ,
    int n4, int full_iters,
    float* __restrict__ out) {
    __shared__ float2 hist[NSLOTS * NT];   // 22,528 B -> 8 CTAs/SM (proven)
    __shared__ float  s_s[NBINS], s_c[NBINS];
    __shared__ bool   s_last;

    const int tid = threadIdx.x;
    #pragma unroll
    for (int i = 0; i < NSLOTS; i++)
        hist[i * NT + tid] = make_float2(0.0f, 0.0f);
    __syncthreads();

    float2* h = &hist[tid];

    int i = blockIdx.x * NT + tid;

    // 4 coalesced LDG.128 front-batched per iter (each touches exactly 4 lines).
    for (int k = 0; k < full_iters; k++) {
        float4 pa = pred[i];
        float4 pb = pred[i + TSTRIDE];
        float4 ta = targ[i];
        float4 tb = targ[i + TSTRIDE];
        ghmc_acc4(pa, ta, h);
        ghmc_acc4(pb, tb, h);
        i += 2 * TSTRIDE;
    }
    // Remainder: plain grid-stride, still coalesced.
    for (; i < n4; i += TSTRIDE) {
        float4 p = pred[i];
        float4 t = targ[i];
        ghmc_acc4(p, t, h);
    }
    __syncthreads();

    // ---- block reduction: 16 threads per bin, each sums 16 columns ----
    if (tid < NBINS * 16) {
        int bin = tid >> 4;
        int j   = tid & 15;
        float sx = 0.0f, sy = 0.0f;
        #pragma unroll
        for (int k = 0; k < NT / 16; k++) {
            float2 a = hist[bin * NT + j + k * 16];
            sx += a.x;
            sy += a.y;
        }
        #pragma unroll
        for (int o = 8; o > 0; o >>= 1) {
            sx += __shfl_down_sync(0xffffffffu, sx, o, 16);
            sy += __shfl_down_sync(0xffffffffu, sy, o, 16);
        }
        if (j == 0)
            g_part[blockIdx.x][bin] = make_float2(sx, sy);
    }

    // ---- last-block final reduction (fused finalize) ----
    __threadfence();
    __syncthreads();
    if (tid == 0) {
        unsigned t = atomicAdd(&g_ticket, 1u);
        s_last = (t == GRID - 1);
    }
    __syncthreads();
    if (!s_last) return;

    __threadfence();
    if (tid < NBINS * 16) {
        int bin = tid >> 4;
        int j   = tid & 15;
        float sx = 0.0f, sy = 0.0f;
        for (int b = j; b < GRID; b += 16) {   // 76 L2-hot loads per thread
            float2 a = g_part[b][bin];
            sx += a.x;
            sy += a.y;
        }
        #pragma unroll
        for (int o = 8; o > 0; o >>= 1) {
            sx += __shfl_down_sync(0xffffffffu, sx, o, 16);
            sy += __shfl_down_sync(0xffffffffu, sy, o, 16);
        }
        if (j == 0) { s_s[bin] = sx; s_c[bin] = sy; }
    }
    __syncthreads();
    if (tid == 0) {
        float n = 0.0f, acc = 0.0f;
        #pragma unroll
        for (int i2 = 0; i2 < NBINS; i2++) {
            if (s_c[i2] > 0.0f) {
                n   += 1.0f;
                acc += s_s[i2] / s_c[i2];
            }
        }
        out[0] = -acc / fmaxf(n, 1.0f);
        g_ticket = 0;   // reset for next graph replay
    }
}

extern "C" void kernel_launch(void* const* d_in, const int* in_sizes, int n_in,
                              void* d_out, int out_size) {
    const float4* pred = (const float4*)d_in[0];
    const float4* targ = (const float4*)d_in[1];
    float* out = (float*)d_out;
    int n  = in_sizes[0];
    int n4 = n >> 2;                          // n divisible by 4
    int full_iters = n4 / (2 * TSTRIDE);      // unrolled main-loop trip count

    ghmc_kernel<<<GRID, NT>>>(pred, targ, n4, full_iters, out);
}

// round 14
// speedup vs baseline: 1.3005x; 1.3005x over previous
#include <cuda_runtime.h>

#define NBINS    10
#define NSLOTS   11          // 10 real bins + 1 dead slot (g >= 1)
#define NT       256
#define GRID_MAX 1280        // upper bound for partials array (>= 8 * numSMs)

// Per-block partials: every block overwrites its own slot -> no zeroing pass.
__device__ float2   g_part[GRID_MAX][NBINS];
__device__ unsigned g_ticket;   // zero-init at load; last block resets each call

__device__ __forceinline__ void ghmc_acc(float p, float t, float2* __restrict__ h) {
    // slot = min(floor(10*|p-t|), 10); slot 10 is dead (discarded later).
    float g10 = fabsf(p - t) * 10.0f;
    int  slot = min((int)g10, NSLOTS - 1);

    // bce = t*p - softplus(p);  softplus(p) = max(p,0) + log(1+exp(-|p|))
    float e   = __expf(-fabsf(p));
    float l   = __logf(1.0f + e);
    float bce = t * p - fmaxf(p, 0.0f) - l;

    float2 a = h[slot * NT];   // stride NT*8B: conflict-free across lanes
    a.x += bce;
    a.y += 1.0f;
    h[slot * NT] = a;
}

__device__ __forceinline__ void ghmc_acc4(float4 p, float4 t,
                                          float2* __restrict__ h) {
    ghmc_acc(p.x, t.x, h);
    ghmc_acc(p.y, t.y, h);
    ghmc_acc(p.z, t.z, h);
    ghmc_acc(p.w, t.w, h);
}

__global__ __launch_bounds__(NT) void ghmc_kernel(
    const float4* __restrict__ pred,
    const float4* __restrict__ targ,
    int n4, int full_iters,
    float* __restrict__ out) {
    __shared__ float2 hist[NSLOTS * NT];   // 22,528 B -> 8 CTAs/SM (proven)
    __shared__ float  s_s[NBINS], s_c[NBINS];
    __shared__ bool   s_last;

    const int tid     = threadIdx.x;
    const int tstride = gridDim.x * NT;    // uniform; grid sized to 8*numSMs

    #pragma unroll
    for (int i = 0; i < NSLOTS; i++)
        hist[i * NT + tid] = make_float2(0.0f, 0.0f);
    __syncthreads();

    float2* h = &hist[tid];

    int i = blockIdx.x * NT + tid;

    // 4 coalesced LDG.128 front-batched per iter (each touches exactly 4 lines).
    for (int k = 0; k < full_iters; k++) {
        float4 pa = pred[i];
        float4 pb = pred[i + tstride];
        float4 ta = targ[i];
        float4 tb = targ[i + tstride];
        ghmc_acc4(pa, ta, h);
        ghmc_acc4(pb, tb, h);
        i += 2 * tstride;
    }
    // Remainder: plain grid-stride, still coalesced.
    for (; i < n4; i += tstride) {
        float4 p = pred[i];
        float4 t = targ[i];
        ghmc_acc4(p, t, h);
    }
    __syncthreads();

    // ---- block reduction: 16 threads per bin, each sums 16 columns ----
    if (tid < NBINS * 16) {
        int bin = tid >> 4;
        int j   = tid & 15;
        float sx = 0.0f, sy = 0.0f;
        #pragma unroll
        for (int k = 0; k < NT / 16; k++) {
            float2 a = hist[bin * NT + j + k * 16];
            sx += a.x;
            sy += a.y;
        }
        #pragma unroll
        for (int o = 8; o > 0; o >>= 1) {
            sx += __shfl_down_sync(0xffffffffu, sx, o, 16);
            sy += __shfl_down_sync(0xffffffffu, sy, o, 16);
        }
        if (j == 0)
            g_part[blockIdx.x][bin] = make_float2(sx, sy);
    }

    // ---- last-block final reduction (fused finalize) ----
    __threadfence();
    __syncthreads();
    if (tid == 0) {
        unsigned t = atomicAdd(&g_ticket, 1u);
        s_last = (t == gridDim.x - 1);
    }
    __syncthreads();
    if (!s_last) return;

    __threadfence();
    if (tid < NBINS * 16) {
        int bin = tid >> 4;
        int j   = tid & 15;
        float sx = 0.0f, sy = 0.0f;
        for (int b = j; b < (int)gridDim.x; b += 16) {   // L2-hot partials
            float2 a = g_part[b][bin];
            sx += a.x;
            sy += a.y;
        }
        #pragma unroll
        for (int o = 8; o > 0; o >>= 1) {
            sx += __shfl_down_sync(0xffffffffu, sx, o, 16);
            sy += __shfl_down_sync(0xffffffffu, sy, o, 16);
        }
        if (j == 0) { s_s[bin] = sx; s_c[bin] = sy; }
    }
    __syncthreads();
    if (tid == 0) {
        float n = 0.0f, acc = 0.0f;
        #pragma unroll
        for (int i2 = 0; i2 < NBINS; i2++) {
            if (s_c[i2] > 0.0f) {
                n   += 1.0f;
                acc += s_s[i2] / s_c[i2];
            }
        }
        out[0] = -acc / fmaxf(n, 1.0f);
        g_ticket = 0;   // reset for next graph replay
    }
}

extern "C" void kernel_launch(void* const* d_in, const int* in_sizes, int n_in,
                              void* d_out, int out_size) {
    const float4* pred = (const float4*)d_in[0];
    const float4* targ = (const float4*)d_in[1];
    float* out = (float*)d_out;
    int n  = in_sizes[0];
    int n4 = n >> 2;                          // n divisible by 4

    // Exactly one resident wave: 8 CTAs per *actual* SM. Attribute query is
    // host-side only (no stream op, no alloc) -> graph-capture safe; the grid
    // dim is baked into the captured graph.
    int dev = 0, nsm = 0;
    cudaGetDevice(&dev);
    cudaDeviceGetAttribute(&nsm, cudaDevAttrMultiProcessorCount, dev);
    if (nsm <= 0 || 8 * nsm > GRID_MAX) nsm = 152;   // fallback
    int grid = 8 * nsm;

    int tstride    = grid * NT;
    int full_iters = n4 / (2 * tstride);      // unrolled main-loop trip count

    ghmc_kernel<<<grid, NT>>>(pred, targ, n4, full_iters, out);
}